// round 11
// baseline (speedup 1.0000x reference)
#include <cuda_runtime.h>
#include <cuda_bf16.h>
#include <cstdint>

typedef __nv_bfloat16 bf16;

#define BATCH 8192
#define NCLUS 4096
#define DIM   3072

// ---- device scratch (allocation-free contract: __device__ globals) ----
__device__ bf16  g_Xb [(size_t)BATCH * DIM];   // x bf16 (K-major)
__device__ bf16  g_Mb [(size_t)NCLUS * DIM];   // means bf16 (K-major, GEMM1 B)
__device__ bf16  g_MbT[(size_t)DIM * NCLUS];   // means^T bf16 (K-major, GEMM2 B)
__device__ float g_psum[(size_t)BATCH * 16];   // per-(row, n-chunk) partial exp sums
__device__ bf16  g_P [(size_t)BATCH * NCLUS];  // exp(scale*dot) bf16 (unnormalized)

// ============================ PTX helpers ============================
__device__ __forceinline__ uint32_t smem_u32(const void* p) {
    uint32_t a;
    asm("{ .reg .u64 t; cvta.to.shared.u64 t, %1; cvt.u32.u64 %0, t; }" : "=r"(a) : "l"(p));
    return a;
}
#define CP_ASYNC16(sa, ga) \
    asm volatile("cp.async.cg.shared.global [%0], [%1], 16;" :: "r"(sa), "l"(ga) : "memory")
#define CP_COMMIT()   asm volatile("cp.async.commit_group;" ::: "memory")
#define CP_WAIT_ALL() asm volatile("cp.async.wait_group 0;" ::: "memory")
#define SWZ(off) ((off) ^ (((off) >> 3) & 0x70))

#define LDSM_X4(r0, r1, r2, r3, addr) \
    asm volatile("ldmatrix.sync.aligned.m8n8.x4.shared.b16 {%0,%1,%2,%3}, [%4];" \
                 : "=r"(r0), "=r"(r1), "=r"(r2), "=r"(r3) : "r"(addr))

#define MMA16816(c0, c1, c2, c3, a0, a1, a2, a3, b0, b1) \
    asm volatile("mma.sync.aligned.m16n8k16.row.col.f32.bf16.bf16.f32 " \
                 "{%0,%1,%2,%3}, {%4,%5,%6,%7}, {%8,%9}, {%0,%1,%2,%3};" \
                 : "+f"(c0), "+f"(c1), "+f"(c2), "+f"(c3) \
                 : "r"(a0), "r"(a1), "r"(a2), "r"(a3), "r"(b0), "r"(b1))

// ============================ prep kernels ============================
__global__ __launch_bounds__(256) void convert_x(const float* __restrict__ src)
{
    const int row = blockIdx.x;
    const int tid = threadIdx.x;
    const float4* s4 = reinterpret_cast<const float4*>(src + (size_t)row * DIM);
    uint2* d2p = reinterpret_cast<uint2*>(g_Xb + (size_t)row * DIM);
    for (int i = tid; i < DIM / 4; i += 256) {
        float4 v = s4[i];
        __nv_bfloat162 lo = __floats2bfloat162_rn(v.x, v.y);
        __nv_bfloat162 hi = __floats2bfloat162_rn(v.z, v.w);
        uint2 u;
        u.x = *reinterpret_cast<unsigned int*>(&lo);
        u.y = *reinterpret_cast<unsigned int*>(&hi);
        d2p[i] = u;
    }
}

// Single pass over means: writes g_Mb (row-major bf16) and g_MbT (transposed bf16).
__global__ __launch_bounds__(256) void convert_means(const float* __restrict__ means)
{
    __shared__ float tile[32][33];
    const int nb = blockIdx.x * 32, db = blockIdx.y * 32;
    const int tx = threadIdx.x & 31, ty = threadIdx.x >> 5;   // 32 x 8
    #pragma unroll
    for (int i = ty; i < 32; i += 8) {
        float v = means[(size_t)(nb + i) * DIM + db + tx];
        tile[i][tx] = v;
        g_Mb[(size_t)(nb + i) * DIM + db + tx] = __float2bfloat16(v);
    }
    __syncthreads();
    #pragma unroll
    for (int i = ty; i < 32; i += 8)
        g_MbT[(size_t)(db + i) * NCLUS + nb + tx] = __float2bfloat16(tile[tx][i]);
}

// ============================ HMMA GEMM ============================
// C[m,n] = sum_k A[m,k] * B[n,k]  (A row-major MxK, B row-major NxK, bf16)
// TM=64, 128 threads (4 warps, 1x4), warp tile 64x(TN/4), BK=64, 2-stage.
// MODE 0: TN=256, 2 CTAs/SM.  MODE 1: TN=192, 3 CTAs/SM (regs clamped to 170).
#define TM 64

template<int MODE>
__global__ __launch_bounds__(128, (MODE == 0) ? 2 : 3)
void gemm_hmma(const float* __restrict__ tptr,
               const float* __restrict__ sdptr,
               const float* __restrict__ xin,
               float* __restrict__ out)
{
    constexpr int K   = (MODE == 0) ? DIM : NCLUS;
    constexpr int nk  = K / 64;                 // 48 or 64 k-tiles
    constexpr int TNm = (MODE == 0) ? 256 : 192;
    constexpr int NI  = TNm / 32;               // 8 or 6
    constexpr int NPI = NI / 2;                 // 4 or 3
    constexpr int WN  = TNm / 4;                // 64 or 48
    constexpr int STAGE_BYTES = TM * 128 + TNm * 128;   // 40KB or 32KB

    const bf16* __restrict__ Ag = (MODE == 0) ? g_Xb : g_P;
    const bf16* __restrict__ Bg = (MODE == 0) ? g_Mb : g_MbT;

    const int m0  = blockIdx.y * TM;
    const int n0  = blockIdx.x * TNm;
    const int tid = threadIdx.x;
    const int wid = tid >> 5, lane = tid & 31;
    const int wn  = wid;               // 0..3 -> WN-col slab (wm == 0)

    extern __shared__ __align__(1024) char dynraw[];
    const uint32_t dyn = smem_u32(dynraw);

    __shared__ float s_rinv[TM];       // MODE 1
    __shared__ float s_part[TM][4];    // MODE 0
    if (MODE == 1 && tid < TM) {
        const float* pp = g_psum + (size_t)(m0 + tid) * 16;
        float s = 0.f;
        #pragma unroll
        for (int j = 0; j < 16; j++) s += pp[j];
        s_rinv[tid] = 1.0f / s;
    }

    auto loadTile = [&](int st, int kt) {
        const uint32_t sa = dyn + st * STAGE_BYTES;
        const uint32_t sb = sa + TM * 128;
        const bf16* Ab = Ag + (size_t)m0 * K + kt * 64;
        const bf16* Bb = Bg + (size_t)n0 * K + kt * 64;
        #pragma unroll
        for (int i = 0; i < 4; i++) {              // A: 512 chunks of 16B
            int chunk = i * 128 + tid;
            int r = chunk >> 3, c16 = chunk & 7;
            CP_ASYNC16(sa + SWZ((uint32_t)chunk * 16), Ab + (size_t)r * K + c16 * 8);
        }
        #pragma unroll
        for (int i = 0; i < TNm / 16; i++) {       // B: TNm*8 chunks of 16B
            int chunk = i * 128 + tid;
            int r = chunk >> 3, c16 = chunk & 7;
            CP_ASYNC16(sb + SWZ((uint32_t)chunk * 16), Bb + (size_t)r * K + c16 * 8);
        }
    };

    float acc[4][NI][4];
    #pragma unroll
    for (int mi = 0; mi < 4; mi++)
        #pragma unroll
        for (int ni = 0; ni < NI; ni++)
            #pragma unroll
            for (int q = 0; q < 4; q++) acc[mi][ni][q] = 0.f;

    loadTile(0, 0); CP_COMMIT();

    const int a_row  = (lane & 15);                              // + mi*16
    const int a_c16  = (lane >> 4);
    const int b_row  = wn * WN + ((lane >> 4) & 1) * 8 + (lane & 7);
    const int b_c16  = (lane >> 3) & 1;

    for (int kt = 0; kt < nk; kt++) {
        CP_WAIT_ALL();
        __syncthreads();
        if (kt + 1 < nk) { loadTile((kt + 1) & 1, kt + 1); CP_COMMIT(); }

        const uint32_t sa = dyn + (kt & 1) * STAGE_BYTES;
        const uint32_t sb = sa + TM * 128;

        #pragma unroll
        for (int ks = 0; ks < 4; ks++) {        // 4 k-steps of 16 elems
            uint32_t af[4][4];
            #pragma unroll
            for (int mi = 0; mi < 4; mi++) {
                uint32_t off = (uint32_t)(a_row + mi * 16) * 128 + ks * 32 + a_c16 * 16;
                LDSM_X4(af[mi][0], af[mi][1], af[mi][2], af[mi][3], sa + SWZ(off));
            }
            uint32_t bfr[NI][2];
            #pragma unroll
            for (int pi = 0; pi < NPI; pi++) {
                uint32_t off = (uint32_t)(b_row + pi * 16) * 128 + ks * 32 + b_c16 * 16;
                LDSM_X4(bfr[pi*2][0], bfr[pi*2][1], bfr[pi*2+1][0], bfr[pi*2+1][1], sb + SWZ(off));
            }
            #pragma unroll
            for (int mi = 0; mi < 4; mi++)
                #pragma unroll
                for (int ni = 0; ni < NI; ni++)
                    MMA16816(acc[mi][ni][0], acc[mi][ni][1], acc[mi][ni][2], acc[mi][ni][3],
                             af[mi][0], af[mi][1], af[mi][2], af[mi][3],
                             bfr[ni][0], bfr[ni][1]);
        }
    }

    // ---- fused epilogue ----
    const float scale = expf(-tptr[0]);
    const float s2    = scale * scale;
    const float sdv   = sdptr[0];
    const float var_t = s2 * sdv * sdv + (1.0f - s2);
    const float dw  = s2 * sdv * sdv / var_t;
    const float w2  = (1.0f - dw) * scale;
    const float isc = 1.0f / scale;

    const int g  = lane >> 2;            // 0..7
    const int tc = (lane & 3) * 2;       // 0,2,4,6

    #pragma unroll
    for (int mi = 0; mi < 4; mi++) {
        const int r0 = m0 + mi * 16 + g;
        float sA = 0.f, sB = 0.f;
        #pragma unroll
        for (int ni = 0; ni < NI; ni++) {
            const int c = n0 + wn * WN + ni * 8 + tc;
            if (MODE == 0) {
                float e0 = __expf(scale * acc[mi][ni][0]);
                float e1 = __expf(scale * acc[mi][ni][1]);
                float e2 = __expf(scale * acc[mi][ni][2]);
                float e3 = __expf(scale * acc[mi][ni][3]);
                sA += e0 + e1; sB += e2 + e3;
                *reinterpret_cast<__nv_bfloat162*>(g_P + (size_t)r0 * NCLUS + c)
                    = __floats2bfloat162_rn(e0, e1);
                *reinterpret_cast<__nv_bfloat162*>(g_P + (size_t)(r0 + 8) * NCLUS + c)
                    = __floats2bfloat162_rn(e2, e3);
            } else {
                const float ri0 = s_rinv[r0 - m0], ri1 = s_rinv[r0 + 8 - m0];
                const float2 x0 = *reinterpret_cast<const float2*>(xin + (size_t)r0 * DIM + c);
                const float2 x1 = *reinterpret_cast<const float2*>(xin + (size_t)(r0 + 8) * DIM + c);
                float2 v0, v1;
                v0.x = (dw * x0.x + w2 * ri0 * acc[mi][ni][0]) * isc;
                v0.y = (dw * x0.y + w2 * ri0 * acc[mi][ni][1]) * isc;
                v1.x = (dw * x1.x + w2 * ri1 * acc[mi][ni][2]) * isc;
                v1.y = (dw * x1.y + w2 * ri1 * acc[mi][ni][3]) * isc;
                *reinterpret_cast<float2*>(out + (size_t)r0 * DIM + c) = v0;
                *reinterpret_cast<float2*>(out + (size_t)(r0 + 8) * DIM + c) = v1;
            }
        }
        if (MODE == 0) {
            sA += __shfl_xor_sync(0xFFFFFFFFu, sA, 1);
            sA += __shfl_xor_sync(0xFFFFFFFFu, sA, 2);
            sB += __shfl_xor_sync(0xFFFFFFFFu, sB, 1);
            sB += __shfl_xor_sync(0xFFFFFFFFu, sB, 2);
            if ((lane & 3) == 0) {
                s_part[mi * 16 + g][wn]     = sA;
                s_part[mi * 16 + 8 + g][wn] = sB;
            }
        }
    }
    if (MODE == 0) {
        __syncthreads();
        if (tid < TM) {
            float s = s_part[tid][0] + s_part[tid][1] + s_part[tid][2] + s_part[tid][3];
            g_psum[(size_t)(m0 + tid) * 16 + blockIdx.x] = s;
        }
    }
}

// ============================ launcher ============================
extern "C" void kernel_launch(void* const* d_in, const int* in_sizes, int n_in,
                              void* d_out, int out_size)
{
    const float* x = nullptr;
    const float* means = nullptr;
    const float* t = nullptr;
    const float* sd = nullptr;
    for (int i = 0; i < n_in; i++) {
        if (in_sizes[i] == BATCH * DIM)      x = (const float*)d_in[i];
        else if (in_sizes[i] == NCLUS * DIM) means = (const float*)d_in[i];
        else if (in_sizes[i] == 1) { if (!t) t = (const float*)d_in[i]; else sd = (const float*)d_in[i]; }
    }
    float* out = (float*)d_out;

    constexpr int SMEM0 = 2 * (TM * 128 + 256 * 128);   // 80KB -> 2 CTAs/SM
    constexpr int SMEM1 = 2 * (TM * 128 + 192 * 128);   // 64KB -> 3 CTAs/SM
    cudaFuncSetAttribute(gemm_hmma<0>, cudaFuncAttributeMaxDynamicSharedMemorySize, SMEM0);
    cudaFuncSetAttribute(gemm_hmma<1>, cudaFuncAttributeMaxDynamicSharedMemorySize, SMEM1);

    convert_x<<<BATCH, 256>>>(x);
    convert_means<<<dim3(NCLUS / 32, DIM / 32), 256>>>(means);

    gemm_hmma<0><<<dim3(NCLUS / 256, BATCH / TM), 128, SMEM0>>>(t, sd, x, out);
    gemm_hmma<1><<<dim3(DIM / 192, BATCH / TM), 128, SMEM1>>>(t, sd, x, out);
}

// round 12
// speedup vs baseline: 1.0540x; 1.0540x over previous
#include <cuda_runtime.h>
#include <cuda_bf16.h>
#include <cstdint>

typedef __nv_bfloat16 bf16;

#define BATCH 8192
#define NCLUS 4096
#define DIM   3072

// ---- device scratch (allocation-free contract: __device__ globals) ----
__device__ bf16  g_Xb [(size_t)BATCH * DIM];   // x bf16 (K-major)
__device__ bf16  g_Mb [(size_t)NCLUS * DIM];   // means bf16 (K-major, GEMM1 B)
__device__ bf16  g_MbT[(size_t)DIM * NCLUS];   // means^T bf16 (K-major, GEMM2 B)
__device__ float g_psum[(size_t)BATCH * 16];   // per-(row, n-chunk) partial exp sums
__device__ bf16  g_P [(size_t)BATCH * NCLUS];  // exp(scale*dot) bf16 (unnormalized)

// ============================ PTX helpers ============================
__device__ __forceinline__ uint32_t smem_u32(const void* p) {
    uint32_t a;
    asm("{ .reg .u64 t; cvta.to.shared.u64 t, %1; cvt.u32.u64 %0, t; }" : "=r"(a) : "l"(p));
    return a;
}
#define CP_ASYNC16(sa, ga) \
    asm volatile("cp.async.cg.shared.global [%0], [%1], 16;" :: "r"(sa), "l"(ga) : "memory")
#define CP_COMMIT()   asm volatile("cp.async.commit_group;" ::: "memory")
#define CP_WAIT_ALL() asm volatile("cp.async.wait_group 0;" ::: "memory")
#define SWZ(off) ((off) ^ (((off) >> 3) & 0x70))

#define LDSM_X4(r0, r1, r2, r3, addr) \
    asm volatile("ldmatrix.sync.aligned.m8n8.x4.shared.b16 {%0,%1,%2,%3}, [%4];" \
                 : "=r"(r0), "=r"(r1), "=r"(r2), "=r"(r3) : "r"(addr))

#define MMA16816(c0, c1, c2, c3, a0, a1, a2, a3, b0, b1) \
    asm volatile("mma.sync.aligned.m16n8k16.row.col.f32.bf16.bf16.f32 " \
                 "{%0,%1,%2,%3}, {%4,%5,%6,%7}, {%8,%9}, {%0,%1,%2,%3};" \
                 : "+f"(c0), "+f"(c1), "+f"(c2), "+f"(c3) \
                 : "r"(a0), "r"(a1), "r"(a2), "r"(a3), "r"(b0), "r"(b1))

// ============================ prep kernels ============================
__global__ __launch_bounds__(256) void convert_x(const float* __restrict__ src)
{
    const int row = blockIdx.x;
    const int tid = threadIdx.x;
    const float4* s4 = reinterpret_cast<const float4*>(src + (size_t)row * DIM);
    uint2* d2p = reinterpret_cast<uint2*>(g_Xb + (size_t)row * DIM);
    for (int i = tid; i < DIM / 4; i += 256) {
        float4 v = s4[i];
        __nv_bfloat162 lo = __floats2bfloat162_rn(v.x, v.y);
        __nv_bfloat162 hi = __floats2bfloat162_rn(v.z, v.w);
        uint2 u;
        u.x = *reinterpret_cast<unsigned int*>(&lo);
        u.y = *reinterpret_cast<unsigned int*>(&hi);
        d2p[i] = u;
    }
}

// Single pass over means: writes g_Mb (row-major bf16) and g_MbT (transposed bf16).
__global__ __launch_bounds__(256) void convert_means(const float* __restrict__ means)
{
    __shared__ float tile[32][33];
    const int nb = blockIdx.x * 32, db = blockIdx.y * 32;
    const int tx = threadIdx.x & 31, ty = threadIdx.x >> 5;   // 32 x 8
    #pragma unroll
    for (int i = ty; i < 32; i += 8) {
        float v = means[(size_t)(nb + i) * DIM + db + tx];
        tile[i][tx] = v;
        g_Mb[(size_t)(nb + i) * DIM + db + tx] = __float2bfloat16(v);
    }
    __syncthreads();
    #pragma unroll
    for (int i = ty; i < 32; i += 8)
        g_MbT[(size_t)(db + i) * NCLUS + nb + tx] = __float2bfloat16(tile[tx][i]);
}

// ============================ HMMA GEMM ============================
// C[m,n] = sum_k A[m,k] * B[n,k]  (A row-major MxK, B row-major NxK, bf16)
// TM=64, 128 threads (4 warps, 1x4), warp tile 64x(TN/4), BK=64, 2-stage,
// 2 CTAs/SM. MODE 1 additionally software-pipelines LDSM fragments.
// MODE 0: TN=256; epi: P=bf16(exp(scale*dot)) + partial rowsums
// MODE 1: TN=192; epi: out = (dw*x + w2*rinv*ct)/scale
#define TM 64

template<int MODE>
__global__ __launch_bounds__(128, 2)
void gemm_hmma(const float* __restrict__ tptr,
               const float* __restrict__ sdptr,
               const float* __restrict__ xin,
               float* __restrict__ out)
{
    constexpr int K   = (MODE == 0) ? DIM : NCLUS;
    constexpr int nk  = K / 64;                 // 48 or 64 k-tiles
    constexpr int TNm = (MODE == 0) ? 256 : 192;
    constexpr int NI  = TNm / 32;               // 8 or 6
    constexpr int NPI = NI / 2;                 // 4 or 3
    constexpr int WN  = TNm / 4;                // 64 or 48
    constexpr int STAGE_BYTES = TM * 128 + TNm * 128;   // 40KB or 32KB

    const bf16* __restrict__ Ag = (MODE == 0) ? g_Xb : g_P;
    const bf16* __restrict__ Bg = (MODE == 0) ? g_Mb : g_MbT;

    const int m0  = blockIdx.y * TM;
    const int n0  = blockIdx.x * TNm;
    const int tid = threadIdx.x;
    const int wid = tid >> 5, lane = tid & 31;
    const int wn  = wid;               // 0..3 -> WN-col slab (wm == 0)

    extern __shared__ __align__(1024) char dynraw[];
    const uint32_t dyn = smem_u32(dynraw);

    __shared__ float s_rinv[TM];       // MODE 1
    __shared__ float s_part[TM][4];    // MODE 0
    if (MODE == 1 && tid < TM) {
        const float* pp = g_psum + (size_t)(m0 + tid) * 16;
        float s = 0.f;
        #pragma unroll
        for (int j = 0; j < 16; j++) s += pp[j];
        s_rinv[tid] = 1.0f / s;
    }

    auto loadTile = [&](int st, int kt) {
        const uint32_t sa = dyn + st * STAGE_BYTES;
        const uint32_t sb = sa + TM * 128;
        const bf16* Ab = Ag + (size_t)m0 * K + kt * 64;
        const bf16* Bb = Bg + (size_t)n0 * K + kt * 64;
        #pragma unroll
        for (int i = 0; i < 4; i++) {              // A: 512 chunks of 16B
            int chunk = i * 128 + tid;
            int r = chunk >> 3, c16 = chunk & 7;
            CP_ASYNC16(sa + SWZ((uint32_t)chunk * 16), Ab + (size_t)r * K + c16 * 8);
        }
        #pragma unroll
        for (int i = 0; i < TNm / 16; i++) {       // B: TNm*8 chunks of 16B
            int chunk = i * 128 + tid;
            int r = chunk >> 3, c16 = chunk & 7;
            CP_ASYNC16(sb + SWZ((uint32_t)chunk * 16), Bb + (size_t)r * K + c16 * 8);
        }
    };

    float acc[4][NI][4];
    #pragma unroll
    for (int mi = 0; mi < 4; mi++)
        #pragma unroll
        for (int ni = 0; ni < NI; ni++)
            #pragma unroll
            for (int q = 0; q < 4; q++) acc[mi][ni][q] = 0.f;

    loadTile(0, 0); CP_COMMIT();

    const int a_row  = (lane & 15);                              // + mi*16
    const int a_c16  = (lane >> 4);
    const int b_row  = wn * WN + ((lane >> 4) & 1) * 8 + (lane & 7);
    const int b_c16  = (lane >> 3) & 1;

    if (MODE == 0) {
        // ---- R10 mainloop (no frag pipelining; acc too large for it) ----
        for (int kt = 0; kt < nk; kt++) {
            CP_WAIT_ALL();
            __syncthreads();
            if (kt + 1 < nk) { loadTile((kt + 1) & 1, kt + 1); CP_COMMIT(); }

            const uint32_t sa = dyn + (kt & 1) * STAGE_BYTES;
            const uint32_t sb = sa + TM * 128;

            #pragma unroll
            for (int ks = 0; ks < 4; ks++) {
                uint32_t af[4][4];
                #pragma unroll
                for (int mi = 0; mi < 4; mi++) {
                    uint32_t off = (uint32_t)(a_row + mi * 16) * 128 + ks * 32 + a_c16 * 16;
                    LDSM_X4(af[mi][0], af[mi][1], af[mi][2], af[mi][3], sa + SWZ(off));
                }
                uint32_t bfr[NI][2];
                #pragma unroll
                for (int pi = 0; pi < NPI; pi++) {
                    uint32_t off = (uint32_t)(b_row + pi * 16) * 128 + ks * 32 + b_c16 * 16;
                    LDSM_X4(bfr[pi*2][0], bfr[pi*2][1], bfr[pi*2+1][0], bfr[pi*2+1][1], sb + SWZ(off));
                }
                #pragma unroll
                for (int mi = 0; mi < 4; mi++)
                    #pragma unroll
                    for (int ni = 0; ni < NI; ni++)
                        MMA16816(acc[mi][ni][0], acc[mi][ni][1], acc[mi][ni][2], acc[mi][ni][3],
                                 af[mi][0], af[mi][1], af[mi][2], af[mi][3],
                                 bfr[ni][0], bfr[ni][1]);
            }
        }
    } else {
        // ---- software-pipelined fragments (double-buffered LDSM) ----
        uint32_t af[2][4][4];
        uint32_t bfr[2][NI][2];

        auto loadFrags = [&](int buf, int ks, uint32_t sa, uint32_t sb) {
            #pragma unroll
            for (int mi = 0; mi < 4; mi++) {
                uint32_t off = (uint32_t)(a_row + mi * 16) * 128 + ks * 32 + a_c16 * 16;
                LDSM_X4(af[buf][mi][0], af[buf][mi][1], af[buf][mi][2], af[buf][mi][3],
                        sa + SWZ(off));
            }
            #pragma unroll
            for (int pi = 0; pi < NPI; pi++) {
                uint32_t off = (uint32_t)(b_row + pi * 16) * 128 + ks * 32 + b_c16 * 16;
                LDSM_X4(bfr[buf][pi*2][0], bfr[buf][pi*2][1],
                        bfr[buf][pi*2+1][0], bfr[buf][pi*2+1][1], sb + SWZ(off));
            }
        };

        for (int kt = 0; kt < nk; kt++) {
            CP_WAIT_ALL();
            __syncthreads();
            if (kt + 1 < nk) { loadTile((kt + 1) & 1, kt + 1); CP_COMMIT(); }

            const uint32_t sa = dyn + (kt & 1) * STAGE_BYTES;
            const uint32_t sb = sa + TM * 128;

            loadFrags(0, 0, sa, sb);
            #pragma unroll
            for (int ks = 0; ks < 4; ks++) {
                const int cur = ks & 1;
                if (ks < 3) loadFrags(cur ^ 1, ks + 1, sa, sb);
                #pragma unroll
                for (int mi = 0; mi < 4; mi++)
                    #pragma unroll
                    for (int ni = 0; ni < NI; ni++)
                        MMA16816(acc[mi][ni][0], acc[mi][ni][1], acc[mi][ni][2], acc[mi][ni][3],
                                 af[cur][mi][0], af[cur][mi][1], af[cur][mi][2], af[cur][mi][3],
                                 bfr[cur][ni][0], bfr[cur][ni][1]);
            }
        }
    }

    // ---- fused epilogue ----
    const float scale = expf(-tptr[0]);
    const float s2    = scale * scale;
    const float sdv   = sdptr[0];
    const float var_t = s2 * sdv * sdv + (1.0f - s2);
    const float dw  = s2 * sdv * sdv / var_t;
    const float w2  = (1.0f - dw) * scale;
    const float isc = 1.0f / scale;

    const int g  = lane >> 2;            // 0..7
    const int tc = (lane & 3) * 2;       // 0,2,4,6

    #pragma unroll
    for (int mi = 0; mi < 4; mi++) {
        const int r0 = m0 + mi * 16 + g;
        float sA = 0.f, sB = 0.f;
        #pragma unroll
        for (int ni = 0; ni < NI; ni++) {
            const int c = n0 + wn * WN + ni * 8 + tc;
            if (MODE == 0) {
                float e0 = __expf(scale * acc[mi][ni][0]);
                float e1 = __expf(scale * acc[mi][ni][1]);
                float e2 = __expf(scale * acc[mi][ni][2]);
                float e3 = __expf(scale * acc[mi][ni][3]);
                sA += e0 + e1; sB += e2 + e3;
                *reinterpret_cast<__nv_bfloat162*>(g_P + (size_t)r0 * NCLUS + c)
                    = __floats2bfloat162_rn(e0, e1);
                *reinterpret_cast<__nv_bfloat162*>(g_P + (size_t)(r0 + 8) * NCLUS + c)
                    = __floats2bfloat162_rn(e2, e3);
            } else {
                const float ri0 = s_rinv[r0 - m0], ri1 = s_rinv[r0 + 8 - m0];
                const float2 x0 = *reinterpret_cast<const float2*>(xin + (size_t)r0 * DIM + c);
                const float2 x1 = *reinterpret_cast<const float2*>(xin + (size_t)(r0 + 8) * DIM + c);
                float2 v0, v1;
                v0.x = (dw * x0.x + w2 * ri0 * acc[mi][ni][0]) * isc;
                v0.y = (dw * x0.y + w2 * ri0 * acc[mi][ni][1]) * isc;
                v1.x = (dw * x1.x + w2 * ri1 * acc[mi][ni][2]) * isc;
                v1.y = (dw * x1.y + w2 * ri1 * acc[mi][ni][3]) * isc;
                *reinterpret_cast<float2*>(out + (size_t)r0 * DIM + c) = v0;
                *reinterpret_cast<float2*>(out + (size_t)(r0 + 8) * DIM + c) = v1;
            }
        }
        if (MODE == 0) {
            sA += __shfl_xor_sync(0xFFFFFFFFu, sA, 1);
            sA += __shfl_xor_sync(0xFFFFFFFFu, sA, 2);
            sB += __shfl_xor_sync(0xFFFFFFFFu, sB, 1);
            sB += __shfl_xor_sync(0xFFFFFFFFu, sB, 2);
            if ((lane & 3) == 0) {
                s_part[mi * 16 + g][wn]     = sA;
                s_part[mi * 16 + 8 + g][wn] = sB;
            }
        }
    }
    if (MODE == 0) {
        __syncthreads();
        if (tid < TM) {
            float s = s_part[tid][0] + s_part[tid][1] + s_part[tid][2] + s_part[tid][3];
            g_psum[(size_t)(m0 + tid) * 16 + blockIdx.x] = s;
        }
    }
}

// ============================ launcher ============================
extern "C" void kernel_launch(void* const* d_in, const int* in_sizes, int n_in,
                              void* d_out, int out_size)
{
    const float* x = nullptr;
    const float* means = nullptr;
    const float* t = nullptr;
    const float* sd = nullptr;
    for (int i = 0; i < n_in; i++) {
        if (in_sizes[i] == BATCH * DIM)      x = (const float*)d_in[i];
        else if (in_sizes[i] == NCLUS * DIM) means = (const float*)d_in[i];
        else if (in_sizes[i] == 1) { if (!t) t = (const float*)d_in[i]; else sd = (const float*)d_in[i]; }
    }
    float* out = (float*)d_out;

    constexpr int SMEM0 = 2 * (TM * 128 + 256 * 128);   // 80KB -> 2 CTAs/SM
    constexpr int SMEM1 = 2 * (TM * 128 + 192 * 128);   // 64KB -> 2 CTAs/SM
    cudaFuncSetAttribute(gemm_hmma<0>, cudaFuncAttributeMaxDynamicSharedMemorySize, SMEM0);
    cudaFuncSetAttribute(gemm_hmma<1>, cudaFuncAttributeMaxDynamicSharedMemorySize, SMEM1);

    convert_x<<<BATCH, 256>>>(x);
    convert_means<<<dim3(NCLUS / 32, DIM / 32), 256>>>(means);

    gemm_hmma<0><<<dim3(NCLUS / 256, BATCH / TM), 128, SMEM0>>>(t, sd, x, out);
    gemm_hmma<1><<<dim3(DIM / 192, BATCH / TM), 128, SMEM1>>>(t, sd, x, out);
}

// round 13
// speedup vs baseline: 1.0906x; 1.0347x over previous
#include <cuda_runtime.h>
#include <cuda_bf16.h>
#include <cstdint>

typedef __nv_bfloat16 bf16;

#define BATCH 8192
#define NCLUS 4096
#define DIM   3072

// ---- device scratch (allocation-free contract: __device__ globals) ----
__device__ bf16  g_Xb [(size_t)BATCH * DIM];   // x bf16 (K-major)
__device__ bf16  g_Mb [(size_t)NCLUS * DIM];   // means bf16 (K-major, GEMM1 B)
__device__ bf16  g_MbT[(size_t)DIM * NCLUS];   // means^T bf16 (K-major, GEMM2 B)
__device__ float g_psum[(size_t)BATCH * 16];   // per-(row, n-chunk) partial exp sums
__device__ bf16  g_P [(size_t)BATCH * NCLUS];  // exp(scale*dot) bf16 (unnormalized)

// ============================ PTX helpers ============================
__device__ __forceinline__ uint32_t smem_u32(const void* p) {
    uint32_t a;
    asm("{ .reg .u64 t; cvta.to.shared.u64 t, %1; cvt.u32.u64 %0, t; }" : "=r"(a) : "l"(p));
    return a;
}
#define CP_ASYNC16(sa, ga) \
    asm volatile("cp.async.cg.shared.global [%0], [%1], 16;" :: "r"(sa), "l"(ga) : "memory")
#define CP_COMMIT()  asm volatile("cp.async.commit_group;" ::: "memory")
#define SWZ(off) ((off) ^ (((off) >> 3) & 0x70))

#define LDSM_X4(r0, r1, r2, r3, addr) \
    asm volatile("ldmatrix.sync.aligned.m8n8.x4.shared.b16 {%0,%1,%2,%3}, [%4];" \
                 : "=r"(r0), "=r"(r1), "=r"(r2), "=r"(r3) : "r"(addr))

#define MMA16816(c0, c1, c2, c3, a0, a1, a2, a3, b0, b1) \
    asm volatile("mma.sync.aligned.m16n8k16.row.col.f32.bf16.bf16.f32 " \
                 "{%0,%1,%2,%3}, {%4,%5,%6,%7}, {%8,%9}, {%0,%1,%2,%3};" \
                 : "+f"(c0), "+f"(c1), "+f"(c2), "+f"(c3) \
                 : "r"(a0), "r"(a1), "r"(a2), "r"(a3), "r"(b0), "r"(b1))

// ============================ prep kernels ============================
__global__ __launch_bounds__(256) void convert_x(const float* __restrict__ src)
{
    const int row = blockIdx.x;
    const int tid = threadIdx.x;
    const float4* s4 = reinterpret_cast<const float4*>(src + (size_t)row * DIM);
    uint2* d2p = reinterpret_cast<uint2*>(g_Xb + (size_t)row * DIM);
    for (int i = tid; i < DIM / 4; i += 256) {
        float4 v = s4[i];
        __nv_bfloat162 lo = __floats2bfloat162_rn(v.x, v.y);
        __nv_bfloat162 hi = __floats2bfloat162_rn(v.z, v.w);
        uint2 u;
        u.x = *reinterpret_cast<unsigned int*>(&lo);
        u.y = *reinterpret_cast<unsigned int*>(&hi);
        d2p[i] = u;
    }
}

// Single pass over means: writes g_Mb (row-major bf16) and g_MbT (transposed bf16).
__global__ __launch_bounds__(256) void convert_means(const float* __restrict__ means)
{
    __shared__ float tile[32][33];
    const int nb = blockIdx.x * 32, db = blockIdx.y * 32;
    const int tx = threadIdx.x & 31, ty = threadIdx.x >> 5;   // 32 x 8
    #pragma unroll
    for (int i = ty; i < 32; i += 8) {
        float v = means[(size_t)(nb + i) * DIM + db + tx];
        tile[i][tx] = v;
        g_Mb[(size_t)(nb + i) * DIM + db + tx] = __float2bfloat16(v);
    }
    __syncthreads();
    #pragma unroll
    for (int i = ty; i < 32; i += 8)
        g_MbT[(size_t)(db + i) * NCLUS + nb + tx] = __float2bfloat16(tile[tx][i]);
}

// ============================ HMMA GEMM ============================
// C[m,n] = sum_k A[m,k] * B[n,k]  (A row-major MxK, B row-major NxK, bf16)
// TM=64, 128 threads (4 warps, 1x4), warp tile 64x(TN/4), BK=64, 2 CTAs/SM,
// LDSM fragment double-buffering in both modes.
// MODE 0: TN=256, 2-stage; epi: P=bf16(exp(scale*dot)) + partial rowsums
// MODE 1: TN=192, 3-stage; epi: out = (dw*x + w2*rinv*ct)/scale
#define TM 64

template<int MODE>
__global__ __launch_bounds__(128, 2)
void gemm_hmma(const float* __restrict__ tptr,
               const float* __restrict__ sdptr,
               const float* __restrict__ xin,
               float* __restrict__ out)
{
    constexpr int K      = (MODE == 0) ? DIM : NCLUS;
    constexpr int nk     = K / 64;               // 48 or 64 k-tiles
    constexpr int TNm    = (MODE == 0) ? 256 : 192;
    constexpr int NI     = TNm / 32;             // 8 or 6
    constexpr int NPI    = NI / 2;               // 4 or 3
    constexpr int WN     = TNm / 4;              // 64 or 48
    constexpr int STAGES = (MODE == 0) ? 2 : 3;
    constexpr int STAGE_BYTES = TM * 128 + TNm * 128;   // 40KB or 32KB

    const bf16* __restrict__ Ag = (MODE == 0) ? g_Xb : g_P;
    const bf16* __restrict__ Bg = (MODE == 0) ? g_Mb : g_MbT;

    const int m0  = blockIdx.y * TM;
    const int n0  = blockIdx.x * TNm;
    const int tid = threadIdx.x;
    const int wid = tid >> 5, lane = tid & 31;
    const int wn  = wid;               // 0..3 -> WN-col slab (wm == 0)

    extern __shared__ __align__(1024) char dynraw[];
    const uint32_t dyn = smem_u32(dynraw);

    __shared__ float s_rinv[TM];       // MODE 1
    __shared__ float s_part[TM][4];    // MODE 0
    if (MODE == 1 && tid < TM) {
        const float* pp = g_psum + (size_t)(m0 + tid) * 16;
        float s = 0.f;
        #pragma unroll
        for (int j = 0; j < 16; j++) s += pp[j];
        s_rinv[tid] = 1.0f / s;
    }

    auto loadTile = [&](int st, int kt) {
        const uint32_t sa = dyn + st * STAGE_BYTES;
        const uint32_t sb = sa + TM * 128;
        const bf16* Ab = Ag + (size_t)m0 * K + kt * 64;
        const bf16* Bb = Bg + (size_t)n0 * K + kt * 64;
        #pragma unroll
        for (int i = 0; i < 4; i++) {              // A: 512 chunks of 16B
            int chunk = i * 128 + tid;
            int r = chunk >> 3, c16 = chunk & 7;
            CP_ASYNC16(sa + SWZ((uint32_t)chunk * 16), Ab + (size_t)r * K + c16 * 8);
        }
        #pragma unroll
        for (int i = 0; i < TNm / 16; i++) {       // B: TNm*8 chunks of 16B
            int chunk = i * 128 + tid;
            int r = chunk >> 3, c16 = chunk & 7;
            CP_ASYNC16(sb + SWZ((uint32_t)chunk * 16), Bb + (size_t)r * K + c16 * 8);
        }
    };

    float acc[4][NI][4];
    #pragma unroll
    for (int mi = 0; mi < 4; mi++)
        #pragma unroll
        for (int ni = 0; ni < NI; ni++)
            #pragma unroll
            for (int q = 0; q < 4; q++) acc[mi][ni][q] = 0.f;

    #pragma unroll
    for (int p = 0; p < STAGES - 1; p++) { loadTile(p, p); CP_COMMIT(); }

    const int a_row  = (lane & 15);                              // + mi*16
    const int a_c16  = (lane >> 4);
    const int b_row  = wn * WN + ((lane >> 4) & 1) * 8 + (lane & 7);
    const int b_c16  = (lane >> 3) & 1;

    uint32_t af[2][4][4];
    uint32_t bfr[2][NI][2];
    auto loadFrags = [&](int buf, int ks, uint32_t sa, uint32_t sb) {
        #pragma unroll
        for (int mi = 0; mi < 4; mi++) {
            uint32_t off = (uint32_t)(a_row + mi * 16) * 128 + ks * 32 + a_c16 * 16;
            LDSM_X4(af[buf][mi][0], af[buf][mi][1], af[buf][mi][2], af[buf][mi][3],
                    sa + SWZ(off));
        }
        #pragma unroll
        for (int pi = 0; pi < NPI; pi++) {
            uint32_t off = (uint32_t)(b_row + pi * 16) * 128 + ks * 32 + b_c16 * 16;
            LDSM_X4(bfr[buf][pi*2][0], bfr[buf][pi*2][1],
                    bfr[buf][pi*2+1][0], bfr[buf][pi*2+1][1], sb + SWZ(off));
        }
    };

    for (int kt = 0; kt < nk; kt++) {
        if (STAGES == 2) asm volatile("cp.async.wait_group 0;" ::: "memory");
        else             asm volatile("cp.async.wait_group 1;" ::: "memory");
        __syncthreads();
        if (kt + STAGES - 1 < nk) loadTile((kt + STAGES - 1) % STAGES, kt + STAGES - 1);
        CP_COMMIT();                    // empty group at tail keeps counts uniform

        const uint32_t sa = dyn + (kt % STAGES) * STAGE_BYTES;
        const uint32_t sb = sa + TM * 128;

        loadFrags(0, 0, sa, sb);
        #pragma unroll
        for (int ks = 0; ks < 4; ks++) {
            const int cur = ks & 1;
            if (ks < 3) loadFrags(cur ^ 1, ks + 1, sa, sb);
            #pragma unroll
            for (int mi = 0; mi < 4; mi++)
                #pragma unroll
                for (int ni = 0; ni < NI; ni++)
                    MMA16816(acc[mi][ni][0], acc[mi][ni][1], acc[mi][ni][2], acc[mi][ni][3],
                             af[cur][mi][0], af[cur][mi][1], af[cur][mi][2], af[cur][mi][3],
                             bfr[cur][ni][0], bfr[cur][ni][1]);
        }
    }

    // ---- fused epilogue ----
    const float scale = expf(-tptr[0]);
    const float s2    = scale * scale;
    const float sdv   = sdptr[0];
    const float var_t = s2 * sdv * sdv + (1.0f - s2);
    const float dw  = s2 * sdv * sdv / var_t;
    const float w2  = (1.0f - dw) * scale;
    const float isc = 1.0f / scale;

    const int g  = lane >> 2;            // 0..7
    const int tc = (lane & 3) * 2;       // 0,2,4,6

    #pragma unroll
    for (int mi = 0; mi < 4; mi++) {
        const int r0 = m0 + mi * 16 + g;
        float sA = 0.f, sB = 0.f;
        #pragma unroll
        for (int ni = 0; ni < NI; ni++) {
            const int c = n0 + wn * WN + ni * 8 + tc;
            if (MODE == 0) {
                float e0 = __expf(scale * acc[mi][ni][0]);
                float e1 = __expf(scale * acc[mi][ni][1]);
                float e2 = __expf(scale * acc[mi][ni][2]);
                float e3 = __expf(scale * acc[mi][ni][3]);
                sA += e0 + e1; sB += e2 + e3;
                *reinterpret_cast<__nv_bfloat162*>(g_P + (size_t)r0 * NCLUS + c)
                    = __floats2bfloat162_rn(e0, e1);
                *reinterpret_cast<__nv_bfloat162*>(g_P + (size_t)(r0 + 8) * NCLUS + c)
                    = __floats2bfloat162_rn(e2, e3);
            } else {
                const float ri0 = s_rinv[r0 - m0], ri1 = s_rinv[r0 + 8 - m0];
                const float2 x0 = *reinterpret_cast<const float2*>(xin + (size_t)r0 * DIM + c);
                const float2 x1 = *reinterpret_cast<const float2*>(xin + (size_t)(r0 + 8) * DIM + c);
                float2 v0, v1;
                v0.x = (dw * x0.x + w2 * ri0 * acc[mi][ni][0]) * isc;
                v0.y = (dw * x0.y + w2 * ri0 * acc[mi][ni][1]) * isc;
                v1.x = (dw * x1.x + w2 * ri1 * acc[mi][ni][2]) * isc;
                v1.y = (dw * x1.y + w2 * ri1 * acc[mi][ni][3]) * isc;
                *reinterpret_cast<float2*>(out + (size_t)r0 * DIM + c) = v0;
                *reinterpret_cast<float2*>(out + (size_t)(r0 + 8) * DIM + c) = v1;
            }
        }
        if (MODE == 0) {
            sA += __shfl_xor_sync(0xFFFFFFFFu, sA, 1);
            sA += __shfl_xor_sync(0xFFFFFFFFu, sA, 2);
            sB += __shfl_xor_sync(0xFFFFFFFFu, sB, 1);
            sB += __shfl_xor_sync(0xFFFFFFFFu, sB, 2);
            if ((lane & 3) == 0) {
                s_part[mi * 16 + g][wn]     = sA;
                s_part[mi * 16 + 8 + g][wn] = sB;
            }
        }
    }
    if (MODE == 0) {
        __syncthreads();
        if (tid < TM) {
            float s = s_part[tid][0] + s_part[tid][1] + s_part[tid][2] + s_part[tid][3];
            g_psum[(size_t)(m0 + tid) * 16 + blockIdx.x] = s;
        }
    }
}

// ============================ launcher ============================
extern "C" void kernel_launch(void* const* d_in, const int* in_sizes, int n_in,
                              void* d_out, int out_size)
{
    const float* x = nullptr;
    const float* means = nullptr;
    const float* t = nullptr;
    const float* sd = nullptr;
    for (int i = 0; i < n_in; i++) {
        if (in_sizes[i] == BATCH * DIM)      x = (const float*)d_in[i];
        else if (in_sizes[i] == NCLUS * DIM) means = (const float*)d_in[i];
        else if (in_sizes[i] == 1) { if (!t) t = (const float*)d_in[i]; else sd = (const float*)d_in[i]; }
    }
    float* out = (float*)d_out;

    constexpr int SMEM0 = 2 * (TM * 128 + 256 * 128);   // 80KB  -> 2 CTAs/SM
    constexpr int SMEM1 = 3 * (TM * 128 + 192 * 128);   // 96KB  -> 2 CTAs/SM
    cudaFuncSetAttribute(gemm_hmma<0>, cudaFuncAttributeMaxDynamicSharedMemorySize, SMEM0);
    cudaFuncSetAttribute(gemm_hmma<1>, cudaFuncAttributeMaxDynamicSharedMemorySize, SMEM1);

    convert_x<<<BATCH, 256>>>(x);
    convert_means<<<dim3(NCLUS / 32, DIM / 32), 256>>>(means);

    gemm_hmma<0><<<dim3(NCLUS / 256, BATCH / TM), 128, SMEM0>>>(t, sd, x, out);
    gemm_hmma<1><<<dim3(DIM / 192, BATCH / TM), 128, SMEM1>>>(t, sd, x, out);
}

// round 14
// speedup vs baseline: 1.1017x; 1.0102x over previous
#include <cuda_runtime.h>
#include <cuda_bf16.h>
#include <cstdint>

typedef __nv_bfloat16 bf16;

#define BATCH 8192
#define NCLUS 4096
#define DIM   3072

// ---- device scratch (allocation-free contract: __device__ globals) ----
__device__ bf16  g_Xb [(size_t)BATCH * DIM];   // x bf16 (K-major)
__device__ bf16  g_Mb [(size_t)NCLUS * DIM];   // means bf16 (K-major, GEMM1 B)
__device__ bf16  g_MbT[(size_t)DIM * NCLUS];   // means^T bf16 (K-major, GEMM2 B)
__device__ float g_psum[(size_t)BATCH * 16];   // per-(row, n-chunk) partial exp sums
__device__ bf16  g_P [(size_t)BATCH * NCLUS];  // exp(scale*dot) bf16 (unnormalized)

// ============================ PTX helpers ============================
__device__ __forceinline__ uint32_t smem_u32(const void* p) {
    uint32_t a;
    asm("{ .reg .u64 t; cvta.to.shared.u64 t, %1; cvt.u32.u64 %0, t; }" : "=r"(a) : "l"(p));
    return a;
}
#define CP_ASYNC16(sa, ga) \
    asm volatile("cp.async.cg.shared.global [%0], [%1], 16;" :: "r"(sa), "l"(ga) : "memory")
#define CP_COMMIT()   asm volatile("cp.async.commit_group;" ::: "memory")
#define CP_WAIT_ALL() asm volatile("cp.async.wait_group 0;" ::: "memory")
#define SWZ(off) ((off) ^ (((off) >> 3) & 0x70))

#define LDSM_X4(r0, r1, r2, r3, addr) \
    asm volatile("ldmatrix.sync.aligned.m8n8.x4.shared.b16 {%0,%1,%2,%3}, [%4];" \
                 : "=r"(r0), "=r"(r1), "=r"(r2), "=r"(r3) : "r"(addr))

#define MMA16816(c0, c1, c2, c3, a0, a1, a2, a3, b0, b1) \
    asm volatile("mma.sync.aligned.m16n8k16.row.col.f32.bf16.bf16.f32 " \
                 "{%0,%1,%2,%3}, {%4,%5,%6,%7}, {%8,%9}, {%0,%1,%2,%3};" \
                 : "+f"(c0), "+f"(c1), "+f"(c2), "+f"(c3) \
                 : "r"(a0), "r"(a1), "r"(a2), "r"(a3), "r"(b0), "r"(b1))

// ============================ prep kernels ============================
__global__ __launch_bounds__(256) void convert_x(const float* __restrict__ src)
{
    const int row = blockIdx.x;
    const int tid = threadIdx.x;
    const float4* s4 = reinterpret_cast<const float4*>(src + (size_t)row * DIM);
    uint2* d2p = reinterpret_cast<uint2*>(g_Xb + (size_t)row * DIM);
    for (int i = tid; i < DIM / 4; i += 256) {
        float4 v = s4[i];
        __nv_bfloat162 lo = __floats2bfloat162_rn(v.x, v.y);
        __nv_bfloat162 hi = __floats2bfloat162_rn(v.z, v.w);
        uint2 u;
        u.x = *reinterpret_cast<unsigned int*>(&lo);
        u.y = *reinterpret_cast<unsigned int*>(&hi);
        d2p[i] = u;
    }
}

// Single pass over means: writes g_Mb (row-major bf16) and g_MbT (transposed bf16).
__global__ __launch_bounds__(256) void convert_means(const float* __restrict__ means)
{
    __shared__ float tile[32][33];
    const int nb = blockIdx.x * 32, db = blockIdx.y * 32;
    const int tx = threadIdx.x & 31, ty = threadIdx.x >> 5;   // 32 x 8
    #pragma unroll
    for (int i = ty; i < 32; i += 8) {
        float v = means[(size_t)(nb + i) * DIM + db + tx];
        tile[i][tx] = v;
        g_Mb[(size_t)(nb + i) * DIM + db + tx] = __float2bfloat16(v);
    }
    __syncthreads();
    #pragma unroll
    for (int i = ty; i < 32; i += 8)
        g_MbT[(size_t)(db + i) * NCLUS + nb + tx] = __float2bfloat16(tile[tx][i]);
}

// ============================ HMMA GEMM ============================
// C[m,n] = sum_k A[m,k] * B[n,k]  (A row-major MxK, B row-major NxK, bf16)
// TM=64, 128 threads (4 warps, 1x4), warp tile 64x(TN/4), BK=64, 2-stage,
// 2 CTAs/SM. First k-step LDSMs issue BEFORE the cp.async burst (barrier shadow).
// MODE 0: TN=256, plain per-ks LDSM (acc too large for frag double-buffer)
// MODE 1: TN=192, frag double-buffered
#define TM 64

template<int MODE>
__global__ __launch_bounds__(128, 2)
void gemm_hmma(const float* __restrict__ tptr,
               const float* __restrict__ sdptr,
               const float* __restrict__ xin,
               float* __restrict__ out)
{
    constexpr int K   = (MODE == 0) ? DIM : NCLUS;
    constexpr int nk  = K / 64;                 // 48 or 64 k-tiles
    constexpr int TNm = (MODE == 0) ? 256 : 192;
    constexpr int NI  = TNm / 32;               // 8 or 6
    constexpr int NPI = NI / 2;                 // 4 or 3
    constexpr int WN  = TNm / 4;                // 64 or 48
    constexpr int STAGE_BYTES = TM * 128 + TNm * 128;   // 40KB or 32KB

    const bf16* __restrict__ Ag = (MODE == 0) ? g_Xb : g_P;
    const bf16* __restrict__ Bg = (MODE == 0) ? g_Mb : g_MbT;

    const int m0  = blockIdx.y * TM;
    const int n0  = blockIdx.x * TNm;
    const int tid = threadIdx.x;
    const int wid = tid >> 5, lane = tid & 31;
    const int wn  = wid;               // 0..3 -> WN-col slab (wm == 0)

    extern __shared__ __align__(1024) char dynraw[];
    const uint32_t dyn = smem_u32(dynraw);

    __shared__ float s_rinv[TM];       // MODE 1
    __shared__ float s_part[TM][4];    // MODE 0
    if (MODE == 1 && tid < TM) {
        const float* pp = g_psum + (size_t)(m0 + tid) * 16;
        float s = 0.f;
        #pragma unroll
        for (int j = 0; j < 16; j++) s += pp[j];
        s_rinv[tid] = 1.0f / s;
    }

    auto loadTile = [&](int st, int kt) {
        const uint32_t sa = dyn + st * STAGE_BYTES;
        const uint32_t sb = sa + TM * 128;
        const bf16* Ab = Ag + (size_t)m0 * K + kt * 64;
        const bf16* Bb = Bg + (size_t)n0 * K + kt * 64;
        #pragma unroll
        for (int i = 0; i < 4; i++) {              // A: 512 chunks of 16B
            int chunk = i * 128 + tid;
            int r = chunk >> 3, c16 = chunk & 7;
            CP_ASYNC16(sa + SWZ((uint32_t)chunk * 16), Ab + (size_t)r * K + c16 * 8);
        }
        #pragma unroll
        for (int i = 0; i < TNm / 16; i++) {       // B: TNm*8 chunks of 16B
            int chunk = i * 128 + tid;
            int r = chunk >> 3, c16 = chunk & 7;
            CP_ASYNC16(sb + SWZ((uint32_t)chunk * 16), Bb + (size_t)r * K + c16 * 8);
        }
        CP_COMMIT();
    };

    float acc[4][NI][4];
    #pragma unroll
    for (int mi = 0; mi < 4; mi++)
        #pragma unroll
        for (int ni = 0; ni < NI; ni++)
            #pragma unroll
            for (int q = 0; q < 4; q++) acc[mi][ni][q] = 0.f;

    loadTile(0, 0);

    const int a_row  = (lane & 15);                              // + mi*16
    const int a_c16  = (lane >> 4);
    const int b_row  = wn * WN + ((lane >> 4) & 1) * 8 + (lane & 7);
    const int b_c16  = (lane >> 3) & 1;

    if (MODE == 0) {
        // ---- plain loop, ks=0 LDSM hoisted ahead of the cp.async burst ----
        for (int kt = 0; kt < nk; kt++) {
            CP_WAIT_ALL();
            __syncthreads();
            const uint32_t sa = dyn + (kt & 1) * STAGE_BYTES;
            const uint32_t sb = sa + TM * 128;

            // ks = 0 fragments first (current stage is resident)
            uint32_t af[4][4];
            uint32_t bfr[NI][2];
            #pragma unroll
            for (int mi = 0; mi < 4; mi++) {
                uint32_t off = (uint32_t)(a_row + mi * 16) * 128 + a_c16 * 16;
                LDSM_X4(af[mi][0], af[mi][1], af[mi][2], af[mi][3], sa + SWZ(off));
            }
            #pragma unroll
            for (int pi = 0; pi < NPI; pi++) {
                uint32_t off = (uint32_t)(b_row + pi * 16) * 128 + b_c16 * 16;
                LDSM_X4(bfr[pi*2][0], bfr[pi*2][1], bfr[pi*2+1][0], bfr[pi*2+1][1], sb + SWZ(off));
            }
            // now the async burst for the next tile
            if (kt + 1 < nk) loadTile((kt + 1) & 1, kt + 1);

            #pragma unroll
            for (int mi = 0; mi < 4; mi++)
                #pragma unroll
                for (int ni = 0; ni < NI; ni++)
                    MMA16816(acc[mi][ni][0], acc[mi][ni][1], acc[mi][ni][2], acc[mi][ni][3],
                             af[mi][0], af[mi][1], af[mi][2], af[mi][3],
                             bfr[ni][0], bfr[ni][1]);

            #pragma unroll
            for (int ks = 1; ks < 4; ks++) {
                #pragma unroll
                for (int mi = 0; mi < 4; mi++) {
                    uint32_t off = (uint32_t)(a_row + mi * 16) * 128 + ks * 32 + a_c16 * 16;
                    LDSM_X4(af[mi][0], af[mi][1], af[mi][2], af[mi][3], sa + SWZ(off));
                }
                #pragma unroll
                for (int pi = 0; pi < NPI; pi++) {
                    uint32_t off = (uint32_t)(b_row + pi * 16) * 128 + ks * 32 + b_c16 * 16;
                    LDSM_X4(bfr[pi*2][0], bfr[pi*2][1], bfr[pi*2+1][0], bfr[pi*2+1][1], sb + SWZ(off));
                }
                #pragma unroll
                for (int mi = 0; mi < 4; mi++)
                    #pragma unroll
                    for (int ni = 0; ni < NI; ni++)
                        MMA16816(acc[mi][ni][0], acc[mi][ni][1], acc[mi][ni][2], acc[mi][ni][3],
                                 af[mi][0], af[mi][1], af[mi][2], af[mi][3],
                                 bfr[ni][0], bfr[ni][1]);
            }
        }
    } else {
        // ---- frag double-buffered; loadFrags(0) before the cp.async burst ----
        uint32_t af[2][4][4];
        uint32_t bfr[2][NI][2];
        auto loadFrags = [&](int buf, int ks, uint32_t sa, uint32_t sb) {
            #pragma unroll
            for (int mi = 0; mi < 4; mi++) {
                uint32_t off = (uint32_t)(a_row + mi * 16) * 128 + ks * 32 + a_c16 * 16;
                LDSM_X4(af[buf][mi][0], af[buf][mi][1], af[buf][mi][2], af[buf][mi][3],
                        sa + SWZ(off));
            }
            #pragma unroll
            for (int pi = 0; pi < NPI; pi++) {
                uint32_t off = (uint32_t)(b_row + pi * 16) * 128 + ks * 32 + b_c16 * 16;
                LDSM_X4(bfr[buf][pi*2][0], bfr[buf][pi*2][1],
                        bfr[buf][pi*2+1][0], bfr[buf][pi*2+1][1], sb + SWZ(off));
            }
        };

        for (int kt = 0; kt < nk; kt++) {
            CP_WAIT_ALL();
            __syncthreads();
            const uint32_t sa = dyn + (kt & 1) * STAGE_BYTES;
            const uint32_t sb = sa + TM * 128;

            loadFrags(0, 0, sa, sb);
            if (kt + 1 < nk) loadTile((kt + 1) & 1, kt + 1);

            #pragma unroll
            for (int ks = 0; ks < 4; ks++) {
                const int cur = ks & 1;
                if (ks < 3) loadFrags(cur ^ 1, ks + 1, sa, sb);
                #pragma unroll
                for (int mi = 0; mi < 4; mi++)
                    #pragma unroll
                    for (int ni = 0; ni < NI; ni++)
                        MMA16816(acc[mi][ni][0], acc[mi][ni][1], acc[mi][ni][2], acc[mi][ni][3],
                                 af[cur][mi][0], af[cur][mi][1], af[cur][mi][2], af[cur][mi][3],
                                 bfr[cur][ni][0], bfr[cur][ni][1]);
            }
        }
    }

    // ---- fused epilogue ----
    const float scale = expf(-tptr[0]);
    const float s2    = scale * scale;
    const float sdv   = sdptr[0];
    const float var_t = s2 * sdv * sdv + (1.0f - s2);
    const float dw  = s2 * sdv * sdv / var_t;
    const float w2  = (1.0f - dw) * scale;
    const float isc = 1.0f / scale;

    const int g  = lane >> 2;            // 0..7
    const int tc = (lane & 3) * 2;       // 0,2,4,6

    #pragma unroll
    for (int mi = 0; mi < 4; mi++) {
        const int r0 = m0 + mi * 16 + g;
        float sA = 0.f, sB = 0.f;
        #pragma unroll
        for (int ni = 0; ni < NI; ni++) {
            const int c = n0 + wn * WN + ni * 8 + tc;
            if (MODE == 0) {
                float e0 = __expf(scale * acc[mi][ni][0]);
                float e1 = __expf(scale * acc[mi][ni][1]);
                float e2 = __expf(scale * acc[mi][ni][2]);
                float e3 = __expf(scale * acc[mi][ni][3]);
                sA += e0 + e1; sB += e2 + e3;
                *reinterpret_cast<__nv_bfloat162*>(g_P + (size_t)r0 * NCLUS + c)
                    = __floats2bfloat162_rn(e0, e1);
                *reinterpret_cast<__nv_bfloat162*>(g_P + (size_t)(r0 + 8) * NCLUS + c)
                    = __floats2bfloat162_rn(e2, e3);
            } else {
                const float ri0 = s_rinv[r0 - m0], ri1 = s_rinv[r0 + 8 - m0];
                const float2 x0 = *reinterpret_cast<const float2*>(xin + (size_t)r0 * DIM + c);
                const float2 x1 = *reinterpret_cast<const float2*>(xin + (size_t)(r0 + 8) * DIM + c);
                float2 v0, v1;
                v0.x = (dw * x0.x + w2 * ri0 * acc[mi][ni][0]) * isc;
                v0.y = (dw * x0.y + w2 * ri0 * acc[mi][ni][1]) * isc;
                v1.x = (dw * x1.x + w2 * ri1 * acc[mi][ni][2]) * isc;
                v1.y = (dw * x1.y + w2 * ri1 * acc[mi][ni][3]) * isc;
                *reinterpret_cast<float2*>(out + (size_t)r0 * DIM + c) = v0;
                *reinterpret_cast<float2*>(out + (size_t)(r0 + 8) * DIM + c) = v1;
            }
        }
        if (MODE == 0) {
            sA += __shfl_xor_sync(0xFFFFFFFFu, sA, 1);
            sA += __shfl_xor_sync(0xFFFFFFFFu, sA, 2);
            sB += __shfl_xor_sync(0xFFFFFFFFu, sB, 1);
            sB += __shfl_xor_sync(0xFFFFFFFFu, sB, 2);
            if ((lane & 3) == 0) {
                s_part[mi * 16 + g][wn]     = sA;
                s_part[mi * 16 + 8 + g][wn] = sB;
            }
        }
    }
    if (MODE == 0) {
        __syncthreads();
        if (tid < TM) {
            float s = s_part[tid][0] + s_part[tid][1] + s_part[tid][2] + s_part[tid][3];
            g_psum[(size_t)(m0 + tid) * 16 + blockIdx.x] = s;
        }
    }
}

// ============================ launcher ============================
extern "C" void kernel_launch(void* const* d_in, const int* in_sizes, int n_in,
                              void* d_out, int out_size)
{
    const float* x = nullptr;
    const float* means = nullptr;
    const float* t = nullptr;
    const float* sd = nullptr;
    for (int i = 0; i < n_in; i++) {
        if (in_sizes[i] == BATCH * DIM)      x = (const float*)d_in[i];
        else if (in_sizes[i] == NCLUS * DIM) means = (const float*)d_in[i];
        else if (in_sizes[i] == 1) { if (!t) t = (const float*)d_in[i]; else sd = (const float*)d_in[i]; }
    }
    float* out = (float*)d_out;

    constexpr int SMEM0 = 2 * (TM * 128 + 256 * 128);   // 80KB -> 2 CTAs/SM
    constexpr int SMEM1 = 2 * (TM * 128 + 192 * 128);   // 64KB -> 2 CTAs/SM
    cudaFuncSetAttribute(gemm_hmma<0>, cudaFuncAttributeMaxDynamicSharedMemorySize, SMEM0);
    cudaFuncSetAttribute(gemm_hmma<1>, cudaFuncAttributeMaxDynamicSharedMemorySize, SMEM1);

    convert_x<<<BATCH, 256>>>(x);
    convert_means<<<dim3(NCLUS / 32, DIM / 32), 256>>>(means);

    gemm_hmma<0><<<dim3(NCLUS / 256, BATCH / TM), 128, SMEM0>>>(t, sd, x, out);
    gemm_hmma<1><<<dim3(DIM / 192, BATCH / TM), 128, SMEM1>>>(t, sd, x, out);
}